// round 16
// baseline (speedup 1.0000x reference)
#include <cuda_runtime.h>
#include <cuda_fp16.h>
#include <math.h>
#include <stdint.h>

#define NB   4
#define SEQ  2048
#define HID  1024
#define FAC  256
#define NHD  16
#define DK   64
#define ROWS (NB*SEQ)   /* 8192 */
#define BH   (NB*NHD)   /* 64   */

/* linear tiling: 128x64 block, 8 warps of 32x32, fp16 operands (R15 FROZEN) */
#define BM 128
#define BN 64
#define BK 32
#define LDA_H 40
#define LDB_H 40

/* flash geometry: fp16, KT=64, NO P smem (register fragment reuse) */
#define KT   64
#define NCH  (SEQ/KT)    /* 32 */
#define LDH  72          /* 144B row stride */
#define HOFF_Q  0
#define HOFF_K  (128*LDH)               /* 9216  */
#define HOFF_V  (HOFF_K + 2*KT*LDH)     /* 18432 */
#define HOFF_MB (HOFF_V + 2*DK*LDH)     /* 27648 halves = 55296 B */
#define FLASH_SMEM (HOFF_MB*2 + 2*KT*4) /* 55808 B */

/* 0.125 * log2(e): Q prescale so scores land in the log2 domain */
#define QSCALE 0.1803368801111204f

/* ---------------- scratch ------------------------------------------------ */
__device__ __half g_q  [ROWS*HID];
__device__ __half g_k  [ROWS*HID];
__device__ __half g_vt [BH*DK*SEQ];   /* V transposed: [bh][d][token] */
__device__ __half g_h  [ROWS*FAC];
__device__ __half g_cv [ROWS*HID];

/* ---------------- helpers ------------------------------------------------ */
__device__ __forceinline__ uint32_t h2pack(float a, float b) {
    __half2 h = __floats2half2_rn(a, b);
    return *(uint32_t*)&h;
}
__device__ __forceinline__ float ex2(float x) {
    float y;
    asm("ex2.approx.f32 %0, %1;" : "=f"(y) : "f"(x));
    return y;
}
__device__ __forceinline__ void mma_f16(float c[4], const uint32_t a[4], const uint32_t b[2]) {
    asm volatile(
        "mma.sync.aligned.m16n8k16.row.col.f32.f16.f16.f32 "
        "{%0,%1,%2,%3}, {%4,%5,%6,%7}, {%8,%9}, {%0,%1,%2,%3};"
        : "+f"(c[0]), "+f"(c[1]), "+f"(c[2]), "+f"(c[3])
        : "r"(a[0]), "r"(a[1]), "r"(a[2]), "r"(a[3]), "r"(b[0]), "r"(b[1]));
}
__device__ __forceinline__ void ldsm4(uint32_t f[4], uint32_t addr) {
    asm volatile("ldmatrix.sync.aligned.m8n8.x4.shared.b16 {%0,%1,%2,%3}, [%4];"
        : "=r"(f[0]), "=r"(f[1]), "=r"(f[2]), "=r"(f[3]) : "r"(addr));
}
__device__ __forceinline__ uint32_t smem_u32(const void* p) {
    return (uint32_t)__cvta_generic_to_shared(p);
}
__device__ __forceinline__ void cpa16(uint32_t dst, const void* src) {
    asm volatile("cp.async.cg.shared.global [%0], [%1], 16;" :: "r"(dst), "l"(src));
}
#define CPA_COMMIT() asm volatile("cp.async.commit_group;" ::: "memory")
#define CPA_WAIT0()  asm volatile("cp.async.wait_group 0;" ::: "memory")

__device__ __forceinline__ uint32_t fb_m_h(uint32_t base, int row0, int lane, int ldh) {
    int lr = lane & 7, sel = lane >> 3;
    int row = row0 + lr + ((sel & 1) << 3);
    int colb = (sel & 2) * 8;
    return base + (uint32_t)(row*ldh)*2u + colb;
}
__device__ __forceinline__ uint32_t fb_n_h(uint32_t base, int n0, int lane, int ldh) {
    int lr = lane & 7, sel = lane >> 3;
    int row = n0 + lr + ((sel & 2) << 2);
    int colb = (sel & 1) * 16;
    return base + (uint32_t)(row*ldh)*2u + colb;
}

/* =================== fp16 linear (templated A dtype, R15 FROZEN) =========
   act: 0 = bias, fp32 out; 1 = bias+leaky(0.2), half out;
        2 = bias, half out; 3 = bias, half TRANSPOSED into Vt[bh][d][token];
        4 = bias*QSCALE, half out (Q, log2 domain)                          */
template <int AH>
__global__ void __launch_bounds__(256, 3) linear_tc(
    const void* __restrict__ Av, const float* __restrict__ W,
    const float* __restrict__ bias, void* __restrict__ Cv,
    int M, int N, int K, int act)
{
    __shared__ __align__(16) __half As[BM][LDA_H];
    __shared__ __align__(16) __half Bs[BN][LDB_H];

    const int tid = threadIdx.x;
    const int row0 = blockIdx.x * BM;
    const int col0 = blockIdx.y * BN;

    const int arow = tid >> 3, acol4 = (tid & 7) << 2;
    const int bn = tid & 63, bk4 = (tid >> 6) << 2;

    const int wid = tid >> 5, lane = tid & 31;
    const int wm = (wid >> 1) * 32, wn = (wid & 1) * 32;
    const int r = lane >> 2, cq = lane & 3;

    const uint32_t smA = smem_u32(&As[0][0]);
    const uint32_t smB = smem_u32(&Bs[0][0]);
    const uint32_t aB0 = fb_m_h(smA, wm,      lane, LDA_H);
    const uint32_t aB1 = fb_m_h(smA, wm + 16, lane, LDA_H);
    const uint32_t bB0 = fb_n_h(smB, wn,      lane, LDB_H);
    const uint32_t bB1 = fb_n_h(smB, wn + 16, lane, LDB_H);

    float acc[2][4][4];
#pragma unroll
    for (int mt = 0; mt < 2; mt++)
#pragma unroll
        for (int nt = 0; nt < 4; nt++)
#pragma unroll
            for (int i = 0; i < 4; i++) acc[mt][nt][i] = 0.f;

    const float* Af = (const float*)Av;
    const __half* Ah = (const __half*)Av;

    float4 pa[4];
    uint2  pah[4];
    float  pb[2][4];
    const int nch = K / BK;

    if (AH) {
#pragma unroll
        for (int p = 0; p < 4; p++)
            pah[p] = *(const uint2*)(Ah + (size_t)(row0 + arow + 32*p)*K + acol4);
    } else {
#pragma unroll
        for (int p = 0; p < 4; p++)
            pa[p] = *(const float4*)(Af + (size_t)(row0 + arow + 32*p)*K + acol4);
    }
#pragma unroll
    for (int p = 0; p < 2; p++)
#pragma unroll
        for (int j = 0; j < 4; j++)
            pb[p][j] = W[(size_t)(bk4 + 16*p + j)*N + col0 + bn];

    for (int c = 0; c < nch; c++) {
        if (AH) {
#pragma unroll
            for (int p = 0; p < 4; p++)
                *(uint2*)&As[arow + 32*p][acol4] = pah[p];
        } else {
#pragma unroll
            for (int p = 0; p < 4; p++) {
                uint2 h4;
                h4.x = h2pack(pa[p].x, pa[p].y);
                h4.y = h2pack(pa[p].z, pa[p].w);
                *(uint2*)&As[arow + 32*p][acol4] = h4;
            }
        }
#pragma unroll
        for (int p = 0; p < 2; p++) {
            uint2 h4;
            h4.x = h2pack(pb[p][0], pb[p][1]);
            h4.y = h2pack(pb[p][2], pb[p][3]);
            *(uint2*)&Bs[bn][bk4 + 16*p] = h4;
        }
        __syncthreads();

        if (c + 1 < nch) {
            int k0 = (c + 1) * BK;
            if (AH) {
#pragma unroll
                for (int p = 0; p < 4; p++)
                    pah[p] = *(const uint2*)(Ah + (size_t)(row0 + arow + 32*p)*K + k0 + acol4);
            } else {
#pragma unroll
                for (int p = 0; p < 4; p++)
                    pa[p] = *(const float4*)(Af + (size_t)(row0 + arow + 32*p)*K + k0 + acol4);
            }
#pragma unroll
            for (int p = 0; p < 2; p++)
#pragma unroll
                for (int j = 0; j < 4; j++)
                    pb[p][j] = W[(size_t)(k0 + bk4 + 16*p + j)*N + col0 + bn];
        }

#pragma unroll
        for (int kb = 0; kb < 2; kb++) {
            uint32_t af0[4], af1[4], bq0[4], bq1[4];
            ldsm4(af0, aB0 + kb*32);
            ldsm4(af1, aB1 + kb*32);
            ldsm4(bq0, bB0 + kb*32);
            ldsm4(bq1, bB1 + kb*32);
            mma_f16(acc[0][0], af0, &bq0[0]);
            mma_f16(acc[0][1], af0, &bq0[2]);
            mma_f16(acc[0][2], af0, &bq1[0]);
            mma_f16(acc[0][3], af0, &bq1[2]);
            mma_f16(acc[1][0], af1, &bq0[0]);
            mma_f16(acc[1][1], af1, &bq0[2]);
            mma_f16(acc[1][2], af1, &bq1[0]);
            mma_f16(acc[1][3], af1, &bq1[2]);
        }
        __syncthreads();
    }

    float* Cf = (float*)Cv;
    __half* Ch = (__half*)Cv;
#pragma unroll
    for (int mt = 0; mt < 2; mt++)
#pragma unroll
        for (int nt = 0; nt < 4; nt++) {
            int col = col0 + wn + nt*8 + cq*2;
            float b0 = bias[col], b1 = bias[col + 1];
#pragma unroll
            for (int hrow = 0; hrow < 2; hrow++) {
                int row = row0 + wm + mt*16 + r + hrow*8;
                float v0 = acc[mt][nt][hrow*2 + 0] + b0;
                float v1 = acc[mt][nt][hrow*2 + 1] + b1;
                if (act == 1) {
                    v0 = (v0 > 0.f) ? v0 : 0.2f*v0;
                    v1 = (v1 > 0.f) ? v1 : 0.2f*v1;
                } else if (act == 4) {
                    v0 *= QSCALE; v1 *= QSCALE;
                }
                if (act == 0) {
                    *(float2*)&Cf[(size_t)row*N + col] = make_float2(v0, v1);
                } else if (act == 3) {
                    int bb = row >> 11, token = row & (SEQ - 1);
                    int h0 = col >> 6, d0 = col & 63;
                    __half* dst = Ch + ((size_t)(bb*NHD + h0)*DK + d0)*SEQ + token;
                    dst[0]   = __float2half_rn(v0);
                    dst[SEQ] = __float2half_rn(v1);
                } else {
                    *(uint32_t*)&Ch[(size_t)row*N + col] = h2pack(v0, v1);
                }
            }
        }
}

/* =================== Flash attention, fp16, KT=64, register-P ============ */
__global__ void __launch_bounds__(256, 2) flash_tc(
    const __half* __restrict__ Q, const __half* __restrict__ K,
    const __half* __restrict__ Vt, const int* __restrict__ mask,
    __half* __restrict__ Cv)
{
    extern __shared__ __align__(16) char smc[];
    const uint32_t smBase = smem_u32(smc);
    const uint32_t smQ = smBase + HOFF_Q*2u;
    const uint32_t smK[2] = { smBase + HOFF_K*2u, smBase + (HOFF_K + KT*LDH)*2u };
    const uint32_t smV[2] = { smBase + HOFF_V*2u, smBase + (HOFF_V + DK*LDH)*2u };
    const uint32_t smM = smBase + HOFF_MB*2u;
    const int* MBI = (const int*)(smc + HOFF_MB*2);

    const int bh = blockIdx.y;
    const int b = bh >> 4, h = bh & 15;
    const int i0 = blockIdx.x * 128;
    const __half* Qp  = Q  + (size_t)b*SEQ*HID + h*DK;
    const __half* Kp  = K  + (size_t)b*SEQ*HID + h*DK;
    const __half* Vtp = Vt + (size_t)bh*DK*SEQ;
    const int* mrow = mask + b*SEQ;
    __half* Cp = Cv + (size_t)b*SEQ*HID + h*DK;

    const int tid = threadIdx.x;
    const int wid = tid >> 5, lane = tid & 31;
    const int wm = wid * 16;
    const int r = lane >> 2, cq = lane & 3;

    /* prologue: Q tile + chunk 0 K/V + mask */
#pragma unroll
    for (int p = 0; p < 4; p++) {
        int idx = p*256 + tid;
        int row = idx >> 3, u = idx & 7;
        cpa16(smQ + (uint32_t)(row*LDH)*2u + u*16,
              Qp + (size_t)(i0 + row)*HID + u*8);
    }
#pragma unroll
    for (int p = 0; p < 2; p++) {
        int idx = p*256 + tid;
        int krow = idx >> 3, ku = idx & 7;
        cpa16(smK[0] + (uint32_t)(krow*LDH)*2u + ku*16,
              Kp + (size_t)krow*HID + ku*8);
        cpa16(smV[0] + (uint32_t)(krow*LDH)*2u + ku*16,
              Vtp + (size_t)krow*SEQ + ku*8);
    }
    if (tid < 16) cpa16(smM + (uint32_t)(tid*16), mrow + tid*4);
    CPA_COMMIT();

    const uint32_t aQ = fb_m_h(smQ, wm, lane, LDH);
    uint32_t bKf[2][4], bVf[2][4];
#pragma unroll
    for (int buf = 0; buf < 2; buf++)
#pragma unroll
        for (int g = 0; g < 4; g++) {
            bKf[buf][g] = fb_n_h(smK[buf], g*16, lane, LDH);
            bVf[buf][g] = fb_n_h(smV[buf], g*16, lane, LDH);
        }

    float acc_o[8][4];
#pragma unroll
    for (int nt = 0; nt < 8; nt++)
#pragma unroll
        for (int i = 0; i < 4; i++) acc_o[nt][i] = 0.f;
    float m_st[2] = {-1e20f, -1e20f};
    float l_st[2] = {0.f, 0.f};

    for (int c = 0; c < NCH; c++) {
        const int cur = c & 1, nxt = cur ^ 1;

        CPA_WAIT0();
        __syncthreads();

        if (c + 1 < NCH) {
            const size_t k0 = (size_t)(c + 1) * KT;
#pragma unroll
            for (int p = 0; p < 2; p++) {
                int idx = p*256 + tid;
                int krow = idx >> 3, ku = idx & 7;
                cpa16(smK[nxt] + (uint32_t)(krow*LDH)*2u + ku*16,
                      Kp + (k0 + krow)*HID + ku*8);
                cpa16(smV[nxt] + (uint32_t)(krow*LDH)*2u + ku*16,
                      Vtp + (size_t)krow*SEQ + k0 + ku*8);
            }
            if (tid < 16) cpa16(smM + (uint32_t)((nxt*KT + tid*4)*4), mrow + k0 + tid*4);
            CPA_COMMIT();
        }

        /* S = Q @ K^T : 16 rows x 64 keys, 4 k16-blocks: 20 ldsm + 32 mma */
        float acc_s[8][4];
#pragma unroll
        for (int nt = 0; nt < 8; nt++)
#pragma unroll
            for (int i = 0; i < 4; i++) acc_s[nt][i] = 0.f;
#pragma unroll
        for (int kb = 0; kb < 4; kb++) {
            uint32_t af[4];
            ldsm4(af, aQ + kb*32);
#pragma unroll
            for (int g = 0; g < 4; g++) {
                uint32_t bq[4];
                ldsm4(bq, bKf[cur][g] + kb*32);
                mma_f16(acc_s[2*g    ], af, &bq[0]);
                mma_f16(acc_s[2*g + 1], af, &bq[2]);
            }
        }

        /* base-2 online softmax over 64 keys (warp-local rows) */
        const int* mi = MBI + cur*KT;
        float alpha[2];
#pragma unroll
        for (int rr = 0; rr < 2; rr++) {
            float mx = -3.4e38f;
#pragma unroll
            for (int nt = 0; nt < 8; nt++) {
                int j = nt*8 + cq*2;
                float b0 = mi[j]     ? 0.f : -1e20f;
                float b1 = mi[j + 1] ? 0.f : -1e20f;
                float s0 = acc_s[nt][rr*2+0] + b0;
                float s1 = acc_s[nt][rr*2+1] + b1;
                acc_s[nt][rr*2+0] = s0;
                acc_s[nt][rr*2+1] = s1;
                mx = fmaxf(mx, fmaxf(s0, s1));
            }
            mx = fmaxf(mx, __shfl_xor_sync(0xffffffffu, mx, 1));
            mx = fmaxf(mx, __shfl_xor_sync(0xffffffffu, mx, 2));
            float m_new = fmaxf(m_st[rr], mx);
            float a = ex2(m_st[rr] - m_new);
            m_st[rr] = m_new;
            alpha[rr] = a;
            float lsum = 0.f;
#pragma unroll
            for (int nt = 0; nt < 8; nt++)
#pragma unroll
                for (int cc = 0; cc < 2; cc++) {
                    float p = ex2(acc_s[nt][rr*2+cc] - m_new);
                    acc_s[nt][rr*2+cc] = p;
                    lsum += p;
                }
            l_st[rr] = l_st[rr]*a + lsum;
        }
#pragma unroll
        for (int nt = 0; nt < 8; nt++)
#pragma unroll
            for (int i = 0; i < 4; i++) acc_o[nt][i] *= alpha[i>>1];

        /* O += P @ V : P comes straight from registers (C-frag == A-frag).
           A-frag for k16 block kb: rows r/r+8, keys kb*16 + {2cq,2cq+1,(+8)}
           = acc_s[2kb] (c0..c3) and acc_s[2kb+1] (c0..c3), fp16-packed.   */
#pragma unroll
        for (int kb = 0; kb < 4; kb++) {
            uint32_t af[4];
            af[0] = h2pack(acc_s[2*kb    ][0], acc_s[2*kb    ][1]);
            af[1] = h2pack(acc_s[2*kb    ][2], acc_s[2*kb    ][3]);
            af[2] = h2pack(acc_s[2*kb + 1][0], acc_s[2*kb + 1][1]);
            af[3] = h2pack(acc_s[2*kb + 1][2], acc_s[2*kb + 1][3]);
#pragma unroll
            for (int g = 0; g < 4; g++) {
                uint32_t bv[4];
                ldsm4(bv, bVf[cur][g] + kb*32);
                mma_f16(acc_o[2*g    ], af, &bv[0]);
                mma_f16(acc_o[2*g + 1], af, &bv[2]);
            }
        }
    }

    float inv2[2];
#pragma unroll
    for (int rr = 0; rr < 2; rr++) {
        float lt = l_st[rr];
        lt += __shfl_xor_sync(0xffffffffu, lt, 1);
        lt += __shfl_xor_sync(0xffffffffu, lt, 2);
        inv2[rr] = 1.f / lt;
    }
#pragma unroll
    for (int nt = 0; nt < 8; nt++) {
        int col = nt*8 + cq*2;
#pragma unroll
        for (int rr = 0; rr < 2; rr++) {
            int row = i0 + wm + rr*8 + r;
            *(uint32_t*)&Cp[(size_t)row*HID + col] =
                h2pack(acc_o[nt][rr*2+0]*inv2[rr], acc_o[nt][rr*2+1]*inv2[rr]);
        }
    }
}

/* ---------------- host orchestration ------------------------------------- */
extern "C" void kernel_launch(void* const* d_in, const int* in_sizes, int n_in,
                              void* d_out, int out_size)
{
    const float* query = (const float*)d_in[0];
    const float* key   = (const float*)d_in[1];
    const float* value = (const float*)d_in[2];
    const int*   mask  = (const int*)  d_in[3];
    const float* Wpq = (const float*)d_in[4],  *bpq = (const float*)d_in[5];
    const float* Wtq = (const float*)d_in[6],  *btq = (const float*)d_in[7];
    const float* Wpk = (const float*)d_in[8],  *bpk = (const float*)d_in[9];
    const float* Wtk = (const float*)d_in[10], *btk = (const float*)d_in[11];
    const float* Wpv = (const float*)d_in[12], *bpv = (const float*)d_in[13];
    const float* Wtv = (const float*)d_in[14], *btv = (const float*)d_in[15];
    const float* Wpo = (const float*)d_in[16], *bpo = (const float*)d_in[17];
    const float* Wto = (const float*)d_in[18], *bto = (const float*)d_in[19];
    float* out = (float*)d_out;

    __half *q_, *k_, *vt_, *h_, *cv_;
    cudaGetSymbolAddress((void**)&q_,  g_q);
    cudaGetSymbolAddress((void**)&k_,  g_k);
    cudaGetSymbolAddress((void**)&vt_, g_vt);
    cudaGetSymbolAddress((void**)&h_,  g_h);
    cudaGetSymbolAddress((void**)&cv_, g_cv);

    cudaFuncSetAttribute(flash_tc, cudaFuncAttributeMaxDynamicSharedMemorySize,
                         FLASH_SMEM);

    dim3 blk(256);
    dim3 gproj(ROWS/BM, FAC/BN);   /* (64, 4)  */
    dim3 gtran(ROWS/BM, HID/BN);   /* (64, 16) */

    linear_tc<0><<<gproj, blk>>>(query, Wpq, bpq, h_, ROWS, FAC, HID, 1);
    linear_tc<1><<<gtran, blk>>>(h_,    Wtq, btq, q_, ROWS, HID, FAC, 4);
    linear_tc<0><<<gproj, blk>>>(key,   Wpk, bpk, h_, ROWS, FAC, HID, 1);
    linear_tc<1><<<gtran, blk>>>(h_,    Wtk, btk, k_, ROWS, HID, FAC, 2);
    linear_tc<0><<<gproj, blk>>>(value, Wpv, bpv, h_, ROWS, FAC, HID, 1);
    linear_tc<1><<<gtran, blk>>>(h_,    Wtv, btv, vt_, ROWS, HID, FAC, 3);

    flash_tc<<<dim3(SEQ/128, BH), blk, FLASH_SMEM>>>(q_, k_, vt_, mask, cv_);

    linear_tc<1><<<gproj, blk>>>(cv_, Wpo, bpo, h_,  ROWS, FAC, HID, 1);
    linear_tc<1><<<gtran, blk>>>(h_,  Wto, bto, out, ROWS, HID, FAC, 0);
}

// round 17
// speedup vs baseline: 1.5151x; 1.5151x over previous
#include <cuda_runtime.h>
#include <cuda_fp16.h>
#include <math.h>
#include <stdint.h>

#define NB   4
#define SEQ  2048
#define HID  1024
#define FAC  256
#define NHD  16
#define DK   64
#define ROWS (NB*SEQ)   /* 8192 */
#define BH   (NB*NHD)   /* 64   */

/* linear tiling: 128x64 block, 8 warps of 32x32, fp16 operands (FROZEN) */
#define BM 128
#define BN 64
#define BK 32
#define LDA_H 40
#define LDB_H 40

/* flash geometry: fp16, KT=64, register-P (no P smem) */
#define KT   64
#define NCH  (SEQ/KT)    /* 32 */
#define LDH  72          /* 144B row stride */
#define HOFF_Q  0
#define HOFF_K  (128*LDH)               /* 9216  */
#define HOFF_V  (HOFF_K + 2*KT*LDH)     /* 18432 */
#define HOFF_MB (HOFF_V + 2*DK*LDH)     /* 27648 halves = 55296 B */
#define FLASH_SMEM (HOFF_MB*2 + 2*KT*4) /* 55808 B */

/* 0.125 * log2(e): Q prescale so scores land in the log2 domain */
#define QSCALE 0.1803368801111204f

/* ---------------- scratch ------------------------------------------------ */
__device__ __half g_q  [ROWS*HID];
__device__ __half g_k  [ROWS*HID];
__device__ __half g_vt [BH*DK*SEQ];   /* V transposed: [bh][d][token] */
__device__ __half g_h  [ROWS*FAC];
__device__ __half g_cv [ROWS*HID];

/* ---------------- helpers ------------------------------------------------ */
__device__ __forceinline__ uint32_t h2pack(float a, float b) {
    __half2 h = __floats2half2_rn(a, b);
    return *(uint32_t*)&h;
}
__device__ __forceinline__ float ex2(float x) {
    float y;
    asm("ex2.approx.f32 %0, %1;" : "=f"(y) : "f"(x));
    return y;
}
__device__ __forceinline__ uint32_t ex2h2(uint32_t x) {
    uint32_t y;
    asm("ex2.approx.f16x2 %0, %1;" : "=r"(y) : "r"(x));
    return y;
}
__device__ __forceinline__ void mma_f16(float c[4], const uint32_t a[4], const uint32_t b[2]) {
    asm volatile(
        "mma.sync.aligned.m16n8k16.row.col.f32.f16.f16.f32 "
        "{%0,%1,%2,%3}, {%4,%5,%6,%7}, {%8,%9}, {%0,%1,%2,%3};"
        : "+f"(c[0]), "+f"(c[1]), "+f"(c[2]), "+f"(c[3])
        : "r"(a[0]), "r"(a[1]), "r"(a[2]), "r"(a[3]), "r"(b[0]), "r"(b[1]));
}
__device__ __forceinline__ void ldsm4(uint32_t f[4], uint32_t addr) {
    asm volatile("ldmatrix.sync.aligned.m8n8.x4.shared.b16 {%0,%1,%2,%3}, [%4];"
        : "=r"(f[0]), "=r"(f[1]), "=r"(f[2]), "=r"(f[3]) : "r"(addr));
}
__device__ __forceinline__ uint32_t smem_u32(const void* p) {
    return (uint32_t)__cvta_generic_to_shared(p);
}
__device__ __forceinline__ void cpa16(uint32_t dst, const void* src) {
    asm volatile("cp.async.cg.shared.global [%0], [%1], 16;" :: "r"(dst), "l"(src));
}
#define CPA_COMMIT() asm volatile("cp.async.commit_group;" ::: "memory")
#define CPA_WAIT0()  asm volatile("cp.async.wait_group 0;" ::: "memory")

__device__ __forceinline__ uint32_t fb_m_h(uint32_t base, int row0, int lane, int ldh) {
    int lr = lane & 7, sel = lane >> 3;
    int row = row0 + lr + ((sel & 1) << 3);
    int colb = (sel & 2) * 8;
    return base + (uint32_t)(row*ldh)*2u + colb;
}
__device__ __forceinline__ uint32_t fb_n_h(uint32_t base, int n0, int lane, int ldh) {
    int lr = lane & 7, sel = lane >> 3;
    int row = n0 + lr + ((sel & 2) << 2);
    int colb = (sel & 1) * 16;
    return base + (uint32_t)(row*ldh)*2u + colb;
}

/* =================== fp16 linear (templated A dtype, FROZEN) =============
   act: 0 = bias, fp32 out; 1 = bias+leaky(0.2), half out;
        2 = bias, half out; 3 = bias, half TRANSPOSED into Vt[bh][d][token];
        4 = bias*QSCALE, half out (Q, log2 domain)                          */
template <int AH>
__global__ void __launch_bounds__(256, 3) linear_tc(
    const void* __restrict__ Av, const float* __restrict__ W,
    const float* __restrict__ bias, void* __restrict__ Cv,
    int M, int N, int K, int act)
{
    __shared__ __align__(16) __half As[BM][LDA_H];
    __shared__ __align__(16) __half Bs[BN][LDB_H];

    const int tid = threadIdx.x;
    const int row0 = blockIdx.x * BM;
    const int col0 = blockIdx.y * BN;

    const int arow = tid >> 3, acol4 = (tid & 7) << 2;
    const int bn = tid & 63, bk4 = (tid >> 6) << 2;

    const int wid = tid >> 5, lane = tid & 31;
    const int wm = (wid >> 1) * 32, wn = (wid & 1) * 32;
    const int r = lane >> 2, cq = lane & 3;

    const uint32_t smA = smem_u32(&As[0][0]);
    const uint32_t smB = smem_u32(&Bs[0][0]);
    const uint32_t aB0 = fb_m_h(smA, wm,      lane, LDA_H);
    const uint32_t aB1 = fb_m_h(smA, wm + 16, lane, LDA_H);
    const uint32_t bB0 = fb_n_h(smB, wn,      lane, LDB_H);
    const uint32_t bB1 = fb_n_h(smB, wn + 16, lane, LDB_H);

    float acc[2][4][4];
#pragma unroll
    for (int mt = 0; mt < 2; mt++)
#pragma unroll
        for (int nt = 0; nt < 4; nt++)
#pragma unroll
            for (int i = 0; i < 4; i++) acc[mt][nt][i] = 0.f;

    const float* Af = (const float*)Av;
    const __half* Ah = (const __half*)Av;

    float4 pa[4];
    uint2  pah[4];
    float  pb[2][4];
    const int nch = K / BK;

    if (AH) {
#pragma unroll
        for (int p = 0; p < 4; p++)
            pah[p] = *(const uint2*)(Ah + (size_t)(row0 + arow + 32*p)*K + acol4);
    } else {
#pragma unroll
        for (int p = 0; p < 4; p++)
            pa[p] = *(const float4*)(Af + (size_t)(row0 + arow + 32*p)*K + acol4);
    }
#pragma unroll
    for (int p = 0; p < 2; p++)
#pragma unroll
        for (int j = 0; j < 4; j++)
            pb[p][j] = W[(size_t)(bk4 + 16*p + j)*N + col0 + bn];

    for (int c = 0; c < nch; c++) {
        if (AH) {
#pragma unroll
            for (int p = 0; p < 4; p++)
                *(uint2*)&As[arow + 32*p][acol4] = pah[p];
        } else {
#pragma unroll
            for (int p = 0; p < 4; p++) {
                uint2 h4;
                h4.x = h2pack(pa[p].x, pa[p].y);
                h4.y = h2pack(pa[p].z, pa[p].w);
                *(uint2*)&As[arow + 32*p][acol4] = h4;
            }
        }
#pragma unroll
        for (int p = 0; p < 2; p++) {
            uint2 h4;
            h4.x = h2pack(pb[p][0], pb[p][1]);
            h4.y = h2pack(pb[p][2], pb[p][3]);
            *(uint2*)&Bs[bn][bk4 + 16*p] = h4;
        }
        __syncthreads();

        if (c + 1 < nch) {
            int k0 = (c + 1) * BK;
            if (AH) {
#pragma unroll
                for (int p = 0; p < 4; p++)
                    pah[p] = *(const uint2*)(Ah + (size_t)(row0 + arow + 32*p)*K + k0 + acol4);
            } else {
#pragma unroll
                for (int p = 0; p < 4; p++)
                    pa[p] = *(const float4*)(Af + (size_t)(row0 + arow + 32*p)*K + k0 + acol4);
            }
#pragma unroll
            for (int p = 0; p < 2; p++)
#pragma unroll
                for (int j = 0; j < 4; j++)
                    pb[p][j] = W[(size_t)(k0 + bk4 + 16*p + j)*N + col0 + bn];
        }

#pragma unroll
        for (int kb = 0; kb < 2; kb++) {
            uint32_t af0[4], af1[4], bq0[4], bq1[4];
            ldsm4(af0, aB0 + kb*32);
            ldsm4(af1, aB1 + kb*32);
            ldsm4(bq0, bB0 + kb*32);
            ldsm4(bq1, bB1 + kb*32);
            mma_f16(acc[0][0], af0, &bq0[0]);
            mma_f16(acc[0][1], af0, &bq0[2]);
            mma_f16(acc[0][2], af0, &bq1[0]);
            mma_f16(acc[0][3], af0, &bq1[2]);
            mma_f16(acc[1][0], af1, &bq0[0]);
            mma_f16(acc[1][1], af1, &bq0[2]);
            mma_f16(acc[1][2], af1, &bq1[0]);
            mma_f16(acc[1][3], af1, &bq1[2]);
        }
        __syncthreads();
    }

    float* Cf = (float*)Cv;
    __half* Ch = (__half*)Cv;
#pragma unroll
    for (int mt = 0; mt < 2; mt++)
#pragma unroll
        for (int nt = 0; nt < 4; nt++) {
            int col = col0 + wn + nt*8 + cq*2;
            float b0 = bias[col], b1 = bias[col + 1];
#pragma unroll
            for (int hrow = 0; hrow < 2; hrow++) {
                int row = row0 + wm + mt*16 + r + hrow*8;
                float v0 = acc[mt][nt][hrow*2 + 0] + b0;
                float v1 = acc[mt][nt][hrow*2 + 1] + b1;
                if (act == 1) {
                    v0 = (v0 > 0.f) ? v0 : 0.2f*v0;
                    v1 = (v1 > 0.f) ? v1 : 0.2f*v1;
                } else if (act == 4) {
                    v0 *= QSCALE; v1 *= QSCALE;
                }
                if (act == 0) {
                    *(float2*)&Cf[(size_t)row*N + col] = make_float2(v0, v1);
                } else if (act == 3) {
                    int bb = row >> 11, token = row & (SEQ - 1);
                    int h0 = col >> 6, d0 = col & 63;
                    __half* dst = Ch + ((size_t)(bb*NHD + h0)*DK + d0)*SEQ + token;
                    dst[0]   = __float2half_rn(v0);
                    dst[SEQ] = __float2half_rn(v1);
                } else {
                    *(uint32_t*)&Ch[(size_t)row*N + col] = h2pack(v0, v1);
                }
            }
        }
}

/* ======= Flash attention: fp16, KT=64, register-P via ex2.f16x2 ========== */
__global__ void __launch_bounds__(256, 2) flash_tc(
    const __half* __restrict__ Q, const __half* __restrict__ K,
    const __half* __restrict__ Vt, const int* __restrict__ mask,
    __half* __restrict__ Cv)
{
    extern __shared__ __align__(16) char smc[];
    const uint32_t smBase = smem_u32(smc);
    const uint32_t smQ = smBase + HOFF_Q*2u;
    const uint32_t smK[2] = { smBase + HOFF_K*2u, smBase + (HOFF_K + KT*LDH)*2u };
    const uint32_t smV[2] = { smBase + HOFF_V*2u, smBase + (HOFF_V + DK*LDH)*2u };
    const uint32_t smM = smBase + HOFF_MB*2u;
    const int* MBI = (const int*)(smc + HOFF_MB*2);

    const int bh = blockIdx.y;
    const int b = bh >> 4, h = bh & 15;
    const int i0 = blockIdx.x * 128;
    const __half* Qp  = Q  + (size_t)b*SEQ*HID + h*DK;
    const __half* Kp  = K  + (size_t)b*SEQ*HID + h*DK;
    const __half* Vtp = Vt + (size_t)bh*DK*SEQ;
    const int* mrow = mask + b*SEQ;
    __half* Cp = Cv + (size_t)b*SEQ*HID + h*DK;

    const int tid = threadIdx.x;
    const int wid = tid >> 5, lane = tid & 31;
    const int wm = wid * 16;
    const int r = lane >> 2, cq = lane & 3;

    /* prologue: Q tile + chunk 0 K/V + mask */
#pragma unroll
    for (int p = 0; p < 4; p++) {
        int idx = p*256 + tid;
        int row = idx >> 3, u = idx & 7;
        cpa16(smQ + (uint32_t)(row*LDH)*2u + u*16,
              Qp + (size_t)(i0 + row)*HID + u*8);
    }
#pragma unroll
    for (int p = 0; p < 2; p++) {
        int idx = p*256 + tid;
        int krow = idx >> 3, ku = idx & 7;
        cpa16(smK[0] + (uint32_t)(krow*LDH)*2u + ku*16,
              Kp + (size_t)krow*HID + ku*8);
        cpa16(smV[0] + (uint32_t)(krow*LDH)*2u + ku*16,
              Vtp + (size_t)krow*SEQ + ku*8);
    }
    if (tid < 16) cpa16(smM + (uint32_t)(tid*16), mrow + tid*4);
    CPA_COMMIT();

    const uint32_t aQ = fb_m_h(smQ, wm, lane, LDH);
    uint32_t bKf[2][4], bVf[2][4];
#pragma unroll
    for (int buf = 0; buf < 2; buf++)
#pragma unroll
        for (int g = 0; g < 4; g++) {
            bKf[buf][g] = fb_n_h(smK[buf], g*16, lane, LDH);
            bVf[buf][g] = fb_n_h(smV[buf], g*16, lane, LDH);
        }

    float acc_o[8][4];
#pragma unroll
    for (int nt = 0; nt < 8; nt++)
#pragma unroll
        for (int i = 0; i < 4; i++) acc_o[nt][i] = 0.f;
    float m_st[2] = {-1e20f, -1e20f};
    float l_st[2] = {0.f, 0.f};

    for (int c = 0; c < NCH; c++) {
        const int cur = c & 1, nxt = cur ^ 1;

        CPA_WAIT0();
        __syncthreads();

        if (c + 1 < NCH) {
            const size_t k0 = (size_t)(c + 1) * KT;
#pragma unroll
            for (int p = 0; p < 2; p++) {
                int idx = p*256 + tid;
                int krow = idx >> 3, ku = idx & 7;
                cpa16(smK[nxt] + (uint32_t)(krow*LDH)*2u + ku*16,
                      Kp + (k0 + krow)*HID + ku*8);
                cpa16(smV[nxt] + (uint32_t)(krow*LDH)*2u + ku*16,
                      Vtp + (size_t)krow*SEQ + k0 + ku*8);
            }
            if (tid < 16) cpa16(smM + (uint32_t)((nxt*KT + tid*4)*4), mrow + k0 + tid*4);
            CPA_COMMIT();
        }

        /* S = Q @ K^T : 16 rows x 64 keys, 4 k16-blocks: 20 ldsm + 32 mma */
        float acc_s[8][4];
#pragma unroll
        for (int nt = 0; nt < 8; nt++)
#pragma unroll
            for (int i = 0; i < 4; i++) acc_s[nt][i] = 0.f;
#pragma unroll
        for (int kb = 0; kb < 4; kb++) {
            uint32_t af[4];
            ldsm4(af, aQ + kb*32);
#pragma unroll
            for (int g = 0; g < 4; g++) {
                uint32_t bq[4];
                ldsm4(bq, bKf[cur][g] + kb*32);
                mma_f16(acc_s[2*g    ], af, &bq[0]);
                mma_f16(acc_s[2*g + 1], af, &bq[2]);
            }
        }

        /* base-2 online softmax; P emitted as packed fp16 via ex2.f16x2 */
        const int* mi = MBI + cur*KT;
        uint32_t pfrag[8][2];
        float alpha[2];
#pragma unroll
        for (int rr = 0; rr < 2; rr++) {
            float mx = -3.4e38f;
#pragma unroll
            for (int nt = 0; nt < 8; nt++) {
                int j = nt*8 + cq*2;
                float b0 = mi[j]     ? 0.f : -1e20f;
                float b1 = mi[j + 1] ? 0.f : -1e20f;
                float s0 = acc_s[nt][rr*2+0] + b0;
                float s1 = acc_s[nt][rr*2+1] + b1;
                acc_s[nt][rr*2+0] = s0;
                acc_s[nt][rr*2+1] = s1;
                mx = fmaxf(mx, fmaxf(s0, s1));
            }
            mx = fmaxf(mx, __shfl_xor_sync(0xffffffffu, mx, 1));
            mx = fmaxf(mx, __shfl_xor_sync(0xffffffffu, mx, 2));
            float m_new = fmaxf(m_st[rr], mx);
            alpha[rr] = ex2(m_st[rr] - m_new);
            m_st[rr] = m_new;
            float lsum = 0.f;
#pragma unroll
            for (int nt = 0; nt < 8; nt++) {
                uint32_t pk = h2pack(acc_s[nt][rr*2+0] - m_new,
                                     acc_s[nt][rr*2+1] - m_new);
                uint32_t pe = ex2h2(pk);
                pfrag[nt][rr] = pe;
                float2 pf = __half22float2(*(__half2*)&pe);
                lsum += pf.x + pf.y;
            }
            l_st[rr] = l_st[rr]*alpha[rr] + lsum;
        }
#pragma unroll
        for (int nt = 0; nt < 8; nt++)
#pragma unroll
            for (int i = 0; i < 4; i++) acc_o[nt][i] *= alpha[i>>1];

        /* O += P @ V : A-fragments come straight from pfrag registers */
#pragma unroll
        for (int kb = 0; kb < 4; kb++) {
            uint32_t af[4];
            af[0] = pfrag[2*kb    ][0];
            af[1] = pfrag[2*kb    ][1];
            af[2] = pfrag[2*kb + 1][0];
            af[3] = pfrag[2*kb + 1][1];
#pragma unroll
            for (int g = 0; g < 4; g++) {
                uint32_t bv[4];
                ldsm4(bv, bVf[cur][g] + kb*32);
                mma_f16(acc_o[2*g    ], af, &bv[0]);
                mma_f16(acc_o[2*g + 1], af, &bv[2]);
            }
        }
    }

    float inv2[2];
#pragma unroll
    for (int rr = 0; rr < 2; rr++) {
        float lt = l_st[rr];
        lt += __shfl_xor_sync(0xffffffffu, lt, 1);
        lt += __shfl_xor_sync(0xffffffffu, lt, 2);
        inv2[rr] = 1.f / lt;
    }
#pragma unroll
    for (int nt = 0; nt < 8; nt++) {
        int col = nt*8 + cq*2;
#pragma unroll
        for (int rr = 0; rr < 2; rr++) {
            int row = i0 + wm + rr*8 + r;
            *(uint32_t*)&Cp[(size_t)row*HID + col] =
                h2pack(acc_o[nt][rr*2+0]*inv2[rr], acc_o[nt][rr*2+1]*inv2[rr]);
        }
    }
}

/* ---------------- host orchestration ------------------------------------- */
extern "C" void kernel_launch(void* const* d_in, const int* in_sizes, int n_in,
                              void* d_out, int out_size)
{
    const float* query = (const float*)d_in[0];
    const float* key   = (const float*)d_in[1];
    const float* value = (const float*)d_in[2];
    const int*   mask  = (const int*)  d_in[3];
    const float* Wpq = (const float*)d_in[4],  *bpq = (const float*)d_in[5];
    const float* Wtq = (const float*)d_in[6],  *btq = (const float*)d_in[7];
    const float* Wpk = (const float*)d_in[8],  *bpk = (const float*)d_in[9];
    const float* Wtk = (const float*)d_in[10], *btk = (const float*)d_in[11];
    const float* Wpv = (const float*)d_in[12], *bpv = (const float*)d_in[13];
    const float* Wtv = (const float*)d_in[14], *btv = (const float*)d_in[15];
    const float* Wpo = (const float*)d_in[16], *bpo = (const float*)d_in[17];
    const float* Wto = (const float*)d_in[18], *bto = (const float*)d_in[19];
    float* out = (float*)d_out;

    __half *q_, *k_, *vt_, *h_, *cv_;
    cudaGetSymbolAddress((void**)&q_,  g_q);
    cudaGetSymbolAddress((void**)&k_,  g_k);
    cudaGetSymbolAddress((void**)&vt_, g_vt);
    cudaGetSymbolAddress((void**)&h_,  g_h);
    cudaGetSymbolAddress((void**)&cv_, g_cv);

    cudaFuncSetAttribute(flash_tc, cudaFuncAttributeMaxDynamicSharedMemorySize,
                         FLASH_SMEM);

    dim3 blk(256);
    dim3 gproj(ROWS/BM, FAC/BN);   /* (64, 4)  */
    dim3 gtran(ROWS/BM, HID/BN);   /* (64, 16) */

    linear_tc<0><<<gproj, blk>>>(query, Wpq, bpq, h_, ROWS, FAC, HID, 1);
    linear_tc<1><<<gtran, blk>>>(h_,    Wtq, btq, q_, ROWS, HID, FAC, 4);
    linear_tc<0><<<gproj, blk>>>(key,   Wpk, bpk, h_, ROWS, FAC, HID, 1);
    linear_tc<1><<<gtran, blk>>>(h_,    Wtk, btk, k_, ROWS, HID, FAC, 2);
    linear_tc<0><<<gproj, blk>>>(value, Wpv, bpv, h_, ROWS, FAC, HID, 1);
    linear_tc<1><<<gtran, blk>>>(h_,    Wtv, btv, vt_, ROWS, HID, FAC, 3);

    flash_tc<<<dim3(SEQ/128, BH), blk, FLASH_SMEM>>>(q_, k_, vt_, mask, cv_);

    linear_tc<1><<<gproj, blk>>>(cv_, Wpo, bpo, h_,  ROWS, FAC, HID, 1);
    linear_tc<1><<<gtran, blk>>>(h_,  Wto, bto, out, ROWS, HID, FAC, 0);
}